// round 2
// baseline (speedup 1.0000x reference)
#include <cuda_runtime.h>
#include <cuda_bf16.h>

// Problem constants (fixed by the reference: b=8, c=512, k=19, h=w=128)
#define B     8
#define C     512
#define K     19
#define KPAD  20          // padded k for pairing
#define KP    10          // k-pairs
#define HW    16384       // 128*128
#define SPLIT 64          // hw split for pooled reduction
#define PCH   (HW / SPLIT)

// K1/K4 tiling
#define T1     256        // threads
#define POS    2          // positions per thread
#define CHUNK  (T1 * POS) // 512 positions per block
#define NCHUNK (HW / CHUNK)

typedef unsigned long long u64;

// ---- static scratch (no allocations allowed) ----
__device__ float g_mask[B * K * HW];            // ~10 MB
__device__ float g_partial[B * SPLIT * K * C];  // ~20 MB
__device__ float g_cf[B * K * C];               // class_feat
__device__ float g_filt[B * K * C];             // filters

// ---- packed f32x2 helpers (SASS FFMA2 path) ----
__device__ __forceinline__ u64 pack2(float x, float y) {
    u64 r; asm("mov.b64 %0, {%1, %2};" : "=l"(r) : "f"(x), "f"(y)); return r;
}
__device__ __forceinline__ void unpack2(u64 v, float& x, float& y) {
    asm("mov.b64 {%0, %1}, %2;" : "=f"(x), "=f"(y) : "l"(v));
}
__device__ __forceinline__ void ffma2(u64& d, u64 a, u64 b) {
    // d = a * b + d   (two independent rn fp32 FMAs)
    asm("fma.rn.f32x2 %0, %1, %2, %0;" : "+l"(d) : "l"(a), "l"(b));
}

__device__ __forceinline__ float sigf(float v) {
    return 1.0f / (1.0f + __expf(-v));
}

// ============================================================
// K1: mask = sigmoid(Wm . x + bm)   [b,k,hw]
// grid (NCHUNK, B), T1 threads, POS positions/thread.
// Weights paired over k in smem: sW[c][20], LDS.64 per k-pair.
// ============================================================
__global__ void k_mask(const float* __restrict__ x,
                       const float* __restrict__ Wm,
                       const float* __restrict__ bm)
{
    __shared__ __align__(16) float sW[C * KPAD];   // 40 KB
    __shared__ __align__(8)  float sb[KPAD];
    const int tid = threadIdx.x;
    const int b = blockIdx.y;

    for (int i = tid; i < C * KPAD; i += T1) {
        int c = i / KPAD, k = i - c * KPAD;
        sW[i] = (k < K) ? Wm[k * C + c] : 0.0f;
    }
    if (tid < KPAD) sb[tid] = (tid < K) ? bm[tid] : 0.0f;
    __syncthreads();

    const int p0 = blockIdx.x * CHUNK + tid * POS;

    u64 acc[POS][KP];
    {
        const u64* bp = reinterpret_cast<const u64*>(sb);
#pragma unroll
        for (int kp = 0; kp < KP; kp++) {
            u64 bv = bp[kp];
            acc[0][kp] = bv;
            acc[1][kp] = bv;
        }
    }

    const float2* xp = reinterpret_cast<const float2*>(
        x + (size_t)b * C * HW + p0);
    const int cstride = HW / 2;

#pragma unroll 4
    for (int c = 0; c < C; c++) {
        float2 v = xp[(size_t)c * cstride];
        u64 d0 = pack2(v.x, v.x);
        u64 d1 = pack2(v.y, v.y);
        const u64* wp = reinterpret_cast<const u64*>(sW + c * KPAD);
#pragma unroll
        for (int kp = 0; kp < KP; kp++) {
            u64 w = wp[kp];
            ffma2(acc[0][kp], d0, w);
            ffma2(acc[1][kp], d1, w);
        }
    }

#pragma unroll
    for (int kp = 0; kp < KP; kp++) {
        float a0k0, a0k1, a1k0, a1k1;
        unpack2(acc[0][kp], a0k0, a0k1);
        unpack2(acc[1][kp], a1k0, a1k1);
        int k0 = 2 * kp, k1 = 2 * kp + 1;
        float2 m0; m0.x = sigf(a0k0); m0.y = sigf(a1k0);
        *reinterpret_cast<float2*>(g_mask + ((size_t)b * K + k0) * HW + p0) = m0;
        if (k1 < K) {
            float2 m1; m1.x = sigf(a0k1); m1.y = sigf(a1k1);
            *reinterpret_cast<float2*>(g_mask + ((size_t)b * K + k1) * HW + p0) = m1;
        }
    }
}

// ============================================================
// K2: partial pooled features (packed over positions).
// grid (SPLIT, B), 256 threads. Thread owns channels {t, t+256};
// 19 class accumulators per channel as f32x2 pairs.
// ============================================================
__global__ void k_pool(const float* __restrict__ x)
{
    __shared__ __align__(16) float ms[K * PCH];   // 19 KB mask tile
    const int tid = threadIdx.x;
    const int s = blockIdx.x;
    const int b = blockIdx.y;
    const int pbase = s * PCH;

    for (int i = tid; i < K * PCH; i += 256) {
        int k = i / PCH;
        int p = i - k * PCH;
        ms[i] = g_mask[((size_t)b * K + k) * HW + pbase + p];
    }
    __syncthreads();

    const int c0 = tid;
    const int c1 = tid + 256;

    u64 acca[K], accb[K];
#pragma unroll
    for (int k = 0; k < K; k++) { acca[k] = 0ull; accb[k] = 0ull; }

    const ulonglong2* xa = reinterpret_cast<const ulonglong2*>(
        x + ((size_t)b * C + c0) * HW + pbase);
    const ulonglong2* xb = reinterpret_cast<const ulonglong2*>(
        x + ((size_t)b * C + c1) * HW + pbase);
    const ulonglong2* msp = reinterpret_cast<const ulonglong2*>(ms);

#pragma unroll 2
    for (int p4 = 0; p4 < PCH / 4; p4++) {
        ulonglong2 va = xa[p4];
        ulonglong2 vb = xb[p4];
#pragma unroll
        for (int k = 0; k < K; k++) {
            ulonglong2 m = msp[k * (PCH / 4) + p4];
            ffma2(acca[k], m.x, va.x);
            ffma2(acca[k], m.y, va.y);
            ffma2(accb[k], m.x, vb.x);
            ffma2(accb[k], m.y, vb.y);
        }
    }

    float* out = g_partial + (((size_t)b * SPLIT + s) * K) * C;
#pragma unroll
    for (int k = 0; k < K; k++) {
        float lo, hi;
        unpack2(acca[k], lo, hi);
        out[(size_t)k * C + c0] = lo + hi;
        unpack2(accb[k], lo, hi);
        out[(size_t)k * C + c1] = lo + hi;
    }
}

// ============================================================
// K2b: reduce partials -> class_feat[b][k][c] / HW
// ============================================================
__global__ void k_reduce()
{
    const int bk = blockIdx.x;
    const int b = bk / K;
    const int k = bk - b * K;
    const int c = threadIdx.x * 4;

    float4 sum = make_float4(0.f, 0.f, 0.f, 0.f);
    for (int s = 0; s < SPLIT; s++) {
        const float4 v = *reinterpret_cast<const float4*>(
            g_partial + (((size_t)b * SPLIT + s) * K + k) * C + c);
        sum.x += v.x; sum.y += v.y; sum.z += v.z; sum.w += v.w;
    }
    const float inv = 1.0f / (float)HW;
    sum.x *= inv; sum.y *= inv; sum.z *= inv; sum.w *= inv;
    *reinterpret_cast<float4*>(g_cf + ((size_t)b * K + k) * C + c) = sum;
}

// ============================================================
// K3: filters[b][k][o] = sum_c Wf[k][o][c]*cf[b][k][c] + bf[k][o]
// grid (B*K), 256 threads (8 warps, warp-per-output)
// ============================================================
__global__ void k_filters(const float* __restrict__ Wf,
                          const float* __restrict__ bf)
{
    __shared__ float cfs[C];
    const int bk = blockIdx.x;
    const int b = bk / K;
    const int k = bk - b * K;
    const int tid = threadIdx.x;
    const int lane = tid & 31;
    const int wid = tid >> 5;

    for (int i = tid; i < C; i += 256)
        cfs[i] = g_cf[((size_t)b * K + k) * C + i];
    __syncthreads();

    for (int o = wid; o < C; o += 8) {
        const float* wrow = Wf + ((size_t)k * C + o) * C;
        float s = 0.f;
        for (int c = lane; c < C; c += 32)
            s += wrow[c] * cfs[c];
#pragma unroll
        for (int off = 16; off > 0; off >>= 1)
            s += __shfl_xor_sync(0xffffffffu, s, off);
        if (lane == 0)
            g_filt[((size_t)b * K + k) * C + o] = s + bf[(size_t)k * C + o];
    }
}

// ============================================================
// K4: pred[b][k][hw] = sum_c filters[b][k][c] * x[b][c][hw]
// Same paired-k structure as K1; no bias, no sigmoid.
// ============================================================
__global__ void k_pred(const float* __restrict__ x,
                       float* __restrict__ out)
{
    __shared__ __align__(16) float sW[C * KPAD];
    const int tid = threadIdx.x;
    const int b = blockIdx.y;

    const float* fb = g_filt + (size_t)b * K * C;
    for (int i = tid; i < C * KPAD; i += T1) {
        int c = i / KPAD, k = i - c * KPAD;
        sW[i] = (k < K) ? fb[(size_t)k * C + c] : 0.0f;
    }
    __syncthreads();

    const int p0 = blockIdx.x * CHUNK + tid * POS;

    u64 acc[POS][KP];
#pragma unroll
    for (int kp = 0; kp < KP; kp++) { acc[0][kp] = 0ull; acc[1][kp] = 0ull; }

    const float2* xp = reinterpret_cast<const float2*>(
        x + (size_t)b * C * HW + p0);
    const int cstride = HW / 2;

#pragma unroll 4
    for (int c = 0; c < C; c++) {
        float2 v = xp[(size_t)c * cstride];
        u64 d0 = pack2(v.x, v.x);
        u64 d1 = pack2(v.y, v.y);
        const u64* wp = reinterpret_cast<const u64*>(sW + c * KPAD);
#pragma unroll
        for (int kp = 0; kp < KP; kp++) {
            u64 w = wp[kp];
            ffma2(acc[0][kp], d0, w);
            ffma2(acc[1][kp], d1, w);
        }
    }

#pragma unroll
    for (int kp = 0; kp < KP; kp++) {
        float a0k0, a0k1, a1k0, a1k1;
        unpack2(acc[0][kp], a0k0, a0k1);
        unpack2(acc[1][kp], a1k0, a1k1);
        int k0 = 2 * kp, k1 = 2 * kp + 1;
        float2 r0; r0.x = a0k0; r0.y = a1k0;
        *reinterpret_cast<float2*>(out + ((size_t)b * K + k0) * HW + p0) = r0;
        if (k1 < K) {
            float2 r1; r1.x = a0k1; r1.y = a1k1;
            *reinterpret_cast<float2*>(out + ((size_t)b * K + k1) * HW + p0) = r1;
        }
    }
}

// ============================================================
// launch
// ============================================================
extern "C" void kernel_launch(void* const* d_in, const int* in_sizes, int n_in,
                              void* d_out, int out_size)
{
    const float* x  = (const float*)d_in[0];
    const float* Wm = (const float*)d_in[1];
    const float* bm = (const float*)d_in[2];
    const float* Wf = (const float*)d_in[3];
    const float* bf = (const float*)d_in[4];
    float* out = (float*)d_out;

    k_mask<<<dim3(NCHUNK, B), T1>>>(x, Wm, bm);
    k_pool<<<dim3(SPLIT, B), 256>>>(x);
    k_reduce<<<B * K, 128>>>();
    k_filters<<<B * K, 256>>>(Wf, bf);
    k_pred<<<dim3(NCHUNK, B), T1>>>(x, out);
}